// round 17
// baseline (speedup 1.0000x reference)
#include <cuda_runtime.h>
#include <math.h>

#define BATCH 4
#define NPTS  8192
#define RT 128                      // rows per compute block
#define CSPLIT 4
#define CPB (NPTS / CSPLIT)         // 2048 cols per compute block
#define CHUNK 256                   // cols staged per chunk
#define NCH (CPB / CHUNK)           // 8 chunks
#define THREADS 256
#define RCH (NPTS / RT)             // 64 row groups per batch
#define NHARV 4                     // harvester blocks (one per batch)
#define NBLK (NHARV + RCH * CSPLIT * BATCH)   // 4 + 1024
#define MST 257                     // padded smem row stride (floats)

__device__ unsigned g_rmax[BATCH * NPTS];   // pred  -> label
__device__ unsigned g_cmax[BATCH * NPTS];   // label -> pred
__device__ unsigned g_rcnt[BATCH * RCH];    // row-group completion counters
__device__ unsigned g_ccnt[BATCH * CSPLIT]; // col-group completion counters
__device__ unsigned g_hdone = 0;            // finished-harvester counter
__device__ float    g_sum = 0.0f;           // global sqrt-sum accumulator

__device__ __forceinline__ unsigned enc(float f) {
    unsigned u = __float_as_uint(f);
    return u ^ ((unsigned)((int)u >> 31) | 0x80000000u);
}
__device__ __forceinline__ float dec(unsigned k) {
    unsigned u = (k & 0x80000000u) ? (k ^ 0x80000000u) : ~k;
    return __uint_as_float(u);
}

// Spin until *cnt >= target (volatile L2 read + nanosleep), then acquire.
__device__ __forceinline__ void wait_cnt(unsigned* cnt, unsigned target) {
    while (*((volatile unsigned*)cnt) < target) __nanosleep(200);
    __threadfence();
}

// One compute block: 128 pred rows x 2048 label cols. Per entry
// u = x.y - x^2/2 - y^2/2 = -d^2/2; BOTH direction maxes use u.
// Harvester blocks (bid < NHARV) consume finished groups concurrently.
__global__ __launch_bounds__(THREADS, 3)
void chamfer_main(const float* __restrict__ pred,
                  const float* __restrict__ label,
                  float* __restrict__ out) {
    const int tid = threadIdx.x;

    if (blockIdx.x < NHARV) {
        // ================= HARVESTER PATH =================
        const int b = blockIdx.x;
        __shared__ float hs[THREADS / 32];
        float s = 0.0f;

        // Row groups of this batch: 128 points each, closed by CSPLIT blocks.
        for (int rc = 0; rc < RCH; rc++) {
            unsigned* cnt = &g_rcnt[b * RCH + rc];
            if (tid == 0) wait_cnt(cnt, CSPLIT);
            __syncthreads();
            __threadfence();
            if (tid < RT) {
                const int i = b * NPTS + rc * RT + tid;
                const unsigned k = g_rmax[i];
                g_rmax[i] = 0u;                         // reset for replay
                s += sqrtf(fmaxf(-2.0f * dec(k), 0.0f));
            }
            if (tid == 0) *cnt = 0u;                    // reset for replay
        }
        // Col groups of this batch: 2048 points each, closed by RCH blocks.
        for (int cs = 0; cs < CSPLIT; cs++) {
            unsigned* cnt = &g_ccnt[b * CSPLIT + cs];
            if (tid == 0) wait_cnt(cnt, RCH);
            __syncthreads();
            __threadfence();
            #pragma unroll
            for (int k4 = 0; k4 < CPB / THREADS; k4++) {
                const int i = b * NPTS + cs * CPB + k4 * THREADS + tid;
                const unsigned k = g_cmax[i];
                g_cmax[i] = 0u;                         // reset for replay
                s += sqrtf(fmaxf(-2.0f * dec(k), 0.0f));
            }
            if (tid == 0) *cnt = 0u;                    // reset for replay
        }

        // Block-reduce this harvester's partial sum.
        #pragma unroll
        for (int off = 16; off > 0; off >>= 1)
            s += __shfl_down_sync(0xFFFFFFFFu, s, off);
        if ((tid & 31) == 0) hs[tid >> 5] = s;
        __syncthreads();
        if (tid == 0) {
            float bs = 0.0f;
            #pragma unroll
            for (int w = 0; w < THREADS / 32; w++) bs += hs[w];
            atomicAdd(&g_sum, bs);
            __threadfence();
            const unsigned done = atomicAdd(&g_hdone, 1u) + 1u;
            if (done == (unsigned)NHARV) {
                __threadfence();                        // all g_sum adds visible
                out[0] = g_sum * (1.0f / (float)(BATCH * NPTS));
                g_sum = 0.0f;                           // reset for replay
                g_hdone = 0u;
            }
        }
        return;
    }

    // ================= COMPUTE PATH (R15 hot loop, unchanged) =================
    const int t  = blockIdx.x - NHARV;
    const int bx = t & 63;                  // row chunk
    const int by = (t >> 6) & 3;            // col split
    const int b  = t >> 8;                  // batch
    const int rbase = bx * RT;
    const int cb    = by * CPB;
    const float* __restrict__ A  = pred  + (size_t)b * NPTS * 3;
    const float* __restrict__ Bp = label + (size_t)b * NPTS * 3;

    __shared__ float4 sB[CHUNK];        // (bx, by, bz, nwy) per col, 4 KB
    __shared__ float  sM[16 * MST];     // merge transpose buffer, ~16 KB

    const int rg  = tid >> 4;
    const int cg  = tid & 15;

    // ---- Prologue: this thread's 8 A rows (96 contiguous bytes) ----
    float ax[8], ay[8], az[8], nwx[8], rowm[8];
    {
        const int r0 = rbase + rg * 8;                  // 16B-aligned start
        const float4* Ar = (const float4*)(A + (size_t)r0 * 3);
        float av[24];
        #pragma unroll
        for (int i = 0; i < 6; i++) *(float4*)&av[4 * i] = Ar[i];
        #pragma unroll
        for (int r = 0; r < 8; r++) {
            ax[r] = av[3 * r + 0];
            ay[r] = av[3 * r + 1];
            az[r] = av[3 * r + 2];
            nwx[r] = -0.5f * fmaf(ax[r], ax[r], fmaf(ay[r], ay[r], az[r] * az[r]));
            rowm[r] = -3.0e38f;
        }
    }

    // Preload chunk 0's column for this thread.
    float nbx, nby, nbz;
    {
        const float* p = Bp + (size_t)(cb + tid) * 3;
        nbx = p[0]; nby = p[1]; nbz = p[2];
    }

    for (int ch = 0; ch < NCH; ch++) {
        __syncthreads();                                // sB free, prev sM reads done
        {
            const float bxx = nbx, byy = nby, bzz = nbz;
            const float nwy = -0.5f * fmaf(bxx, bxx, fmaf(byy, byy, bzz * bzz));
            sB[tid] = make_float4(bxx, byy, bzz, nwy);
        }
        __syncthreads();

        if (ch + 1 < NCH) {                             // prefetch next chunk's col
            const float* p = Bp + (size_t)(cb + (ch + 1) * CHUNK + tid) * 3;
            nbx = p[0]; nby = p[1]; nbz = p[2];
        }

        float colm[16];
        #pragma unroll
        for (int k = 0; k < 16; k++) colm[k] = -3.0e38f;

        // Main compute: 16 cols x 8 rows, scalar FFMA, maxes in regs.
        #pragma unroll
        for (int cc = 0; cc < 16; cc++) {
            const float4 v = sB[cc * 16 + cg];          // consecutive float4s
            float cm = colm[cc];
            #pragma unroll
            for (int r = 0; r < 8; r++) {
                float u = fmaf(az[r], v.z, v.w);        // az*bz - y^2/2
                u = fmaf(ay[r], v.y, u);                // + ay*by
                u = fmaf(ax[r], v.x, u);                // + ax*bx
                u += nwx[r];                            // - x^2/2  => -d^2/2
                rowm[r] = fmaxf(rowm[r], u);
                cm = fmaxf(cm, u);
            }
            colm[cc] = cm;
        }

        // Col merge for this chunk: 16 rg writers per col through sM.
        #pragma unroll
        for (int cc = 0; cc < 16; cc++)
            sM[rg * MST + cc * 16 + cg] = colm[cc];
        __syncthreads();
        {
            float m = sM[tid];
            #pragma unroll
            for (int g = 1; g < 16; g++) m = fmaxf(m, sM[g * MST + tid]);
            atomicMax(&g_cmax[(size_t)b * NPTS + cb + ch * CHUNK + tid], enc(m));
        }
    }

    // ---- Row merge: transpose through smem, one RED per row ----
    __syncthreads();
    #pragma unroll
    for (int r = 0; r < 8; r++)
        sM[cg * MST + rg * 8 + r] = rowm[r];
    __syncthreads();
    if (tid < RT) {
        float m = sM[tid];
        #pragma unroll
        for (int g = 1; g < 16; g++) m = fmaxf(m, sM[g * MST + tid]);
        atomicMax(&g_rmax[(size_t)b * NPTS + rbase + tid], enc(m));
    }

    // ---- Group-completion accounting (release: fence before inc) ----
    __threadfence();
    __syncthreads();
    if (tid == 0) {
        atomicAdd(&g_rcnt[b * RCH + bx], 1u);
        atomicAdd(&g_ccnt[b * CSPLIT + by], 1u);
    }
}

extern "C" void kernel_launch(void* const* d_in, const int* in_sizes, int n_in,
                              void* d_out, int out_size) {
    const float* pred  = (const float*)d_in[0];
    const float* label = (const float*)d_in[1];
    float* out = (float*)d_out;

    chamfer_main<<<NBLK, THREADS>>>(pred, label, out);
}